// round 3
// baseline (speedup 1.0000x reference)
#include <cuda_runtime.h>
#include <cstdint>
#include <cstddef>

#define NN 50000
#define EE 800000
#define HH 128
#define KK 4

// ---------------- scratch (device globals; no allocation allowed) ----------------
__device__ float g_h[(size_t)NN * HH];
__device__ float g_hw[(size_t)NN * HH];
__device__ float g_agg[(size_t)KK * NN * HH];
__device__ float g_dist[EE];
__device__ float g_dsum[EE];
__device__ float g_ab[(size_t)KK * EE];
__device__ float g_sum[KK * HH];
__device__ float g_sumsq[KK * HH];
__device__ float g_sc[KK * HH];
__device__ float g_tc[KK * HH];
__device__ float g_ac[KK * HH];
__device__ unsigned g_maxd;

// ---------------- vectorized global reduction (sm_90+) ----------------
__device__ __forceinline__ void red_add_v4(float* p, float a, float b, float c, float d) {
    asm volatile("red.global.add.v4.f32 [%0], {%1,%2,%3,%4};"
                 :: "l"(p), "f"(a), "f"(b), "f"(c), "f"(d) : "memory");
}

// ---------------- stage 1: C[M,128] = act(A[M,128] @ W[128,128]^T + b) ----------------
__global__ void gemm128_kernel(const float* __restrict__ A, const float* __restrict__ W,
                               const float* __restrict__ bias, float* __restrict__ C,
                               int M, int do_relu) {
    __shared__ float As[32 * 36];   // [cc][m], padded
    __shared__ float Ws[32 * 132];  // [cc][j], padded
    const int t = threadIdx.x;
    const int tn = t & 31, tm = t >> 5;
    const int row0 = blockIdx.x * 32;
    float acc[4][4] = {};

    for (int kc = 0; kc < 128; kc += 32) {
#pragma unroll
        for (int i = 0; i < 4; i++) {
            int lin = t + i * 256;
            int m = lin >> 5, cc = lin & 31;
            int row = row0 + m;
            As[cc * 36 + m] = (row < M) ? A[(size_t)row * 128 + kc + cc] : 0.f;
        }
#pragma unroll
        for (int i = 0; i < 16; i++) {
            int lin = t + i * 256;
            int cc = lin & 31, j = lin >> 5;
            Ws[cc * 132 + j] = W[j * 128 + kc + cc];
        }
        __syncthreads();
#pragma unroll
        for (int cc = 0; cc < 32; cc++) {
            float4 a4 = *(const float4*)(As + cc * 36 + tm * 4);
            float4 b4 = *(const float4*)(Ws + cc * 132 + tn * 4);
            float ar[4] = {a4.x, a4.y, a4.z, a4.w};
            float br[4] = {b4.x, b4.y, b4.z, b4.w};
#pragma unroll
            for (int r = 0; r < 4; r++)
#pragma unroll
                for (int u = 0; u < 4; u++) acc[r][u] += ar[r] * br[u];
        }
        __syncthreads();
    }
    float4 bv = *(const float4*)(bias + tn * 4);
    float bb[4] = {bv.x, bv.y, bv.z, bv.w};
#pragma unroll
    for (int r = 0; r < 4; r++) {
        int row = row0 + tm * 4 + r;
        if (row < M) {
            float4 o;
            o.x = acc[r][0] + bb[0]; o.y = acc[r][1] + bb[1];
            o.z = acc[r][2] + bb[2]; o.w = acc[r][3] + bb[3];
            if (do_relu) {
                o.x = fmaxf(o.x, 0.f); o.y = fmaxf(o.y, 0.f);
                o.z = fmaxf(o.z, 0.f); o.w = fmaxf(o.w, 0.f);
            }
            *(float4*)(C + (size_t)row * 128 + tn * 4) = o;
        }
    }
}

// ---------------- edge pass 1: dist, dsum, global max(dist) ----------------
__global__ void edge_prep1(const int* __restrict__ ei, const float* __restrict__ pos) {
    int e = blockIdx.x * blockDim.x + threadIdx.x;
    float d = 0.f;
    if (e < EE) {
        int s = ei[e], t = ei[EE + e];
        float dx = pos[s * 3 + 0] - pos[t * 3 + 0];
        float dy = pos[s * 3 + 1] - pos[t * 3 + 1];
        float dz = pos[s * 3 + 2] - pos[t * 3 + 2];
        d = sqrtf(dx * dx + dy * dy + dz * dz);
        g_dist[e] = d;
        g_dsum[e] = (dx + dy + dz) / (d + 1e-8f);
    }
#pragma unroll
    for (int o = 16; o; o >>= 1) d = fmaxf(d, __shfl_xor_sync(0xffffffffu, d, o));
    __shared__ float wm[8];
    if ((threadIdx.x & 31) == 0) wm[threadIdx.x >> 5] = d;
    __syncthreads();
    if (threadIdx.x < 8) {
        d = wm[threadIdx.x];
#pragma unroll
        for (int o = 4; o; o >>= 1) d = fmaxf(d, __shfl_xor_sync(0xffu, d, o));
        if (threadIdx.x == 0) atomicMax(&g_maxd, __float_as_uint(d));
    }
}

// ---------------- edge pass 2: per-view aberration factor ab[k][e] ----------------
__global__ void edge_prep2(const float* __restrict__ vf_p, const float* __restrict__ vmax_p) {
    int e = blockIdx.x * blockDim.x + threadIdx.x;
    if (e >= EE) return;
    float md = __uint_as_float(g_maxd);
    float r = g_dist[e] / md;
    float ds = g_dsum[e];
    float vf = vf_p[0];
#pragma unroll
    for (int k = 0; k < KK; k++) {
        float v = vf * fminf(r, vmax_p[k]);
        float ab = sqrtf(1.f - v * v + 1e-8f) / (1.f + v * ds);
        g_ab[(size_t)k * EE + e] = ab;
    }
}

// ---------------- scatter: one warp per edge, 4 views per pass ----------------
__global__ void scatter_kernel(const int* __restrict__ ei) {
    int gt = blockIdx.x * blockDim.x + threadIdx.x;
    int e = gt >> 5, lane = gt & 31;
    if (e >= EE) return;
    int s = ei[e], t = ei[EE + e];
    float4 a = ((const float4*)g_hw)[(size_t)s * 32 + lane];
#pragma unroll
    for (int k = 0; k < KK; k++) {
        float ab = g_ab[(size_t)k * EE + e];
        float* p = g_agg + ((size_t)k * NN + t) * 128 + lane * 4;
        red_add_v4(p, a.x * ab, a.y * ab, a.z * ab, a.w * ab);
    }
}

// ---------------- BN statistics ----------------
__global__ void bn_stats_kernel() {
    int f = threadIdx.x;                       // 0..127
    int k = blockIdx.y;                        // 0..3
    int per = (NN + gridDim.x - 1) / gridDim.x;
    int n0 = blockIdx.x * per;
    int n1 = min(n0 + per, NN);
    float s = 0.f, q = 0.f;
    const float* base = g_agg + (size_t)k * NN * 128 + f;
    for (int n = n0; n < n1; n++) {
        float v = base[(size_t)n * 128];
        s += v; q += v * v;
    }
    atomicAdd(&g_sum[k * 128 + f], s);
    atomicAdd(&g_sumsq[k * 128 + f], q);
}

__global__ void bn_final_kernel(const float* __restrict__ bg, const float* __restrict__ bb,
                                const float* __restrict__ att) {
    int c = threadIdx.x;  // 0..511
    float mean = g_sum[c] * (1.f / NN);
    float var = g_sumsq[c] * (1.f / NN) - mean * mean;
    float rstd = rsqrtf(fmaxf(var, 0.f) + 1e-5f);
    float sc = rstd * bg[c];
    g_sc[c] = sc;
    g_tc[c] = bb[c] - mean * sc;
    g_ac[c] = att[c];
}

// ---------------- fused tail: bn+relu+att -> GEMM1 -> LN+relu -> GEMM2 -> out ----------------
__global__ void fused_out_kernel(const float* __restrict__ W1, const float* __restrict__ b1,
                                 const float* __restrict__ lng, const float* __restrict__ lnb,
                                 const float* __restrict__ W2, const float* __restrict__ b2,
                                 float* __restrict__ out) {
    __shared__ float smem[10432];             // 41728 B union
    float* As = smem;                         // [32][36]   (1152)
    float* Bs = smem + 1152;                  // [32][260]  (8320)
    float* Cs = smem;                         // [32][260]  (8320)  -- reuses As/Bs region
    float* Ws2 = smem + 8320;                 // [16][132]  (2112)
    const int t = threadIdx.x;
    const int tn = t & 31, tm = t >> 5;       // tm = warp id (8 warps)
    const int row0 = blockIdx.x * 32;

    float acc[4][8] = {};
    // GEMM1: [32,512] @ W1^T[512,256], A generated on the fly from agg via bn-normalize
    for (int ch = 0; ch < 16; ch++) {
        int c0 = ch * 32;
#pragma unroll
        for (int i = 0; i < 4; i++) {
            int lin = t + i * 256;
            int m = lin >> 5, cc = lin & 31;
            int cg = c0 + cc;
            int k = cg >> 7, f = cg & 127;
            int row = row0 + m;
            float v = 0.f;
            if (row < NN) {
                float a = g_agg[((size_t)k * NN + row) * 128 + f];
                v = fmaxf(a * g_sc[cg] + g_tc[cg], 0.f) * g_ac[cg];
            }
            As[cc * 36 + m] = v;
        }
#pragma unroll
        for (int i = 0; i < 32; i++) {
            int lin = t + i * 256;
            int cc = lin & 31, j = lin >> 5;
            Bs[cc * 260 + j] = W1[(size_t)j * 512 + c0 + cc];
        }
        __syncthreads();
#pragma unroll
        for (int cc = 0; cc < 32; cc++) {
            float4 a4 = *(const float4*)(As + cc * 36 + tm * 4);
            const float* bp = Bs + cc * 260 + tn * 8;
            float4 bA = *(const float4*)bp;
            float4 bB = *(const float4*)(bp + 4);
            float ar[4] = {a4.x, a4.y, a4.z, a4.w};
            float br[8] = {bA.x, bA.y, bA.z, bA.w, bB.x, bB.y, bB.z, bB.w};
#pragma unroll
            for (int r = 0; r < 4; r++)
#pragma unroll
                for (int u = 0; u < 8; u++) acc[r][u] += ar[r] * br[u];
        }
        __syncthreads();
    }

    // LayerNorm + relu, fully in registers (each warp owns rows tm*4..tm*4+3; lanes span cols)
    float bb_[8], lg[8], lb[8];
#pragma unroll
    for (int u = 0; u < 8; u++) {
        int col = tn * 8 + u;
        bb_[u] = b1[col]; lg[u] = lng[col]; lb[u] = lnb[col];
    }
#pragma unroll
    for (int r = 0; r < 4; r++) {
        float s = 0.f, q = 0.f;
#pragma unroll
        for (int u = 0; u < 8; u++) {
            acc[r][u] += bb_[u];
            s += acc[r][u];
            q += acc[r][u] * acc[r][u];
        }
#pragma unroll
        for (int o = 16; o; o >>= 1) {
            s += __shfl_xor_sync(0xffffffffu, s, o);
            q += __shfl_xor_sync(0xffffffffu, q, o);
        }
        float mu = s * (1.f / 256.f);
        float var = q * (1.f / 256.f) - mu * mu;
        float rstd = rsqrtf(fmaxf(var, 0.f) + 1e-5f);
#pragma unroll
        for (int u = 0; u < 8; u++)
            acc[r][u] = fmaxf((acc[r][u] - mu) * rstd * lg[u] + lb[u], 0.f);
    }
    // store LN'd tile to Cs (safe: last barrier ended all Bs reads)
#pragma unroll
    for (int r = 0; r < 4; r++) {
        float* cp = Cs + (tm * 4 + r) * 260 + tn * 8;
        *(float4*)cp       = make_float4(acc[r][0], acc[r][1], acc[r][2], acc[r][3]);
        *(float4*)(cp + 4) = make_float4(acc[r][4], acc[r][5], acc[r][6], acc[r][7]);
    }
    __syncthreads();

    // GEMM2: [32,256] @ W2^T[256,128]
    float acc2[4][4] = {};
    for (int ch = 0; ch < 16; ch++) {
        int c0 = ch * 16;
#pragma unroll
        for (int i = 0; i < 8; i++) {
            int lin = t + i * 256;
            int cc = lin & 15, j = lin >> 4;
            Ws2[cc * 132 + j] = W2[j * 256 + c0 + cc];
        }
        __syncthreads();
#pragma unroll
        for (int cc = 0; cc < 16; cc++) {
            float4 b4 = *(const float4*)(Ws2 + cc * 132 + tn * 4);
            float br[4] = {b4.x, b4.y, b4.z, b4.w};
#pragma unroll
            for (int r = 0; r < 4; r++) {
                float a = Cs[(tm * 4 + r) * 260 + c0 + cc];
#pragma unroll
                for (int u = 0; u < 4; u++) acc2[r][u] += a * br[u];
            }
        }
        __syncthreads();
    }
    float4 b2v = *(const float4*)(b2 + tn * 4);
    float b2r[4] = {b2v.x, b2v.y, b2v.z, b2v.w};
#pragma unroll
    for (int r = 0; r < 4; r++) {
        int row = row0 + tm * 4 + r;
        if (row < NN) {
            float4 o;
            o.x = acc2[r][0] + b2r[0]; o.y = acc2[r][1] + b2r[1];
            o.z = acc2[r][2] + b2r[2]; o.w = acc2[r][3] + b2r[3];
            *(float4*)(out + (size_t)row * 128 + tn * 4) = o;
        }
    }
}

// ---------------- launch ----------------
extern "C" void kernel_launch(void* const* d_in, const int* in_sizes, int n_in,
                              void* d_out, int out_size) {
    const float* x        = (const float*)d_in[0];
    const int*   ei       = (const int*)  d_in[1];
    const float* pos      = (const float*)d_in[2];
    const float* W_ft     = (const float*)d_in[3];
    const float* b_ft     = (const float*)d_in[4];
    const float* W_conv   = (const float*)d_in[5];
    const float* b_conv   = (const float*)d_in[6];
    const float* vf       = (const float*)d_in[7];
    const float* vparams  = (const float*)d_in[8];
    const float* bn_gamma = (const float*)d_in[9];
    const float* bn_beta  = (const float*)d_in[10];
    const float* attention= (const float*)d_in[11];
    const float* W1       = (const float*)d_in[12];
    const float* b1       = (const float*)d_in[13];
    const float* lng      = (const float*)d_in[14];
    const float* lnb      = (const float*)d_in[15];
    const float* W2       = (const float*)d_in[16];
    const float* b2       = (const float*)d_in[17];
    float* out = (float*)d_out;

    void *p_agg, *p_sum, *p_sumsq, *p_maxd, *p_h, *p_hw;
    cudaGetSymbolAddress(&p_agg, g_agg);
    cudaGetSymbolAddress(&p_sum, g_sum);
    cudaGetSymbolAddress(&p_sumsq, g_sumsq);
    cudaGetSymbolAddress(&p_maxd, g_maxd);
    cudaGetSymbolAddress(&p_h, g_h);
    cudaGetSymbolAddress(&p_hw, g_hw);

    cudaMemsetAsync(p_agg, 0, (size_t)KK * NN * HH * sizeof(float));
    cudaMemsetAsync(p_sum, 0, KK * HH * sizeof(float));
    cudaMemsetAsync(p_sumsq, 0, KK * HH * sizeof(float));
    cudaMemsetAsync(p_maxd, 0, sizeof(unsigned));

    // stage 1: h = relu(x @ W_ft^T + b_ft); hw = h @ W_conv^T + b_conv
    gemm128_kernel<<<(NN + 31) / 32, 256>>>(x, W_ft, b_ft, (float*)p_h, NN, 1);
    gemm128_kernel<<<(NN + 31) / 32, 256>>>((const float*)p_h, W_conv, b_conv, (float*)p_hw, NN, 0);

    // edge geometry
    edge_prep1<<<(EE + 255) / 256, 256>>>(ei, pos);
    edge_prep2<<<(EE + 255) / 256, 256>>>(vf, vparams);

    // scatter-add (one warp per edge, all 4 views)
    scatter_kernel<<<(EE * 32) / 256, 256>>>(ei);

    // batch-norm statistics and fold
    bn_stats_kernel<<<dim3(128, KK), 128>>>();
    bn_final_kernel<<<1, KK * HH>>>(bn_gamma, bn_beta, attention);

    // fused tail
    fused_out_kernel<<<(NN + 31) / 32, 256>>>(W1, b1, lng, lnb, W2, b2, out);
}

// round 6
// speedup vs baseline: 1.2272x; 1.2272x over previous
#include <cuda_runtime.h>
#include <cstdint>
#include <cstddef>

#define NN 50000
#define EE 800000
#define HH 128
#define KK 4
#define SCAN_B 1024
#define NCHUNK ((NN + SCAN_B - 1) / SCAN_B)   // 49

// ---------------- scratch (device globals; no allocation allowed) ----------------
__device__ float g_hw[(size_t)NN * HH];
__device__ float g_agg[(size_t)KK * NN * HH];
__device__ float g_dist[EE];
__device__ float g_dsum[EE];
__device__ int   g_deg[NN];
__device__ int   g_cur[NN];
__device__ int   g_scan[NN];
__device__ int   g_btot[NCHUNK];
__device__ int   g_base[NN + 1];
__device__ int   g_srcs[EE];
__device__ float4 g_ab4[EE];
__device__ float g_sum[KK * HH];
__device__ float g_sumsq[KK * HH];
__device__ float g_sc[KK * HH];
__device__ float g_tc[KK * HH];
__device__ float g_ac[KK * HH];
__device__ unsigned g_maxd;

// ---------------- fused stage 1: hw = relu(x @ Wft^T + bft) @ Wconv^T + bconv ----------------
__global__ __launch_bounds__(256) void mlp2_kernel(
    const float* __restrict__ x, const float* __restrict__ Wft, const float* __restrict__ bft,
    const float* __restrict__ Wconv, const float* __restrict__ bconv,
    float* __restrict__ out, int M) {
    __shared__ float As[32 * 36];    // [cc][m]
    __shared__ float Ws[32 * 132];   // [cc][j]
    __shared__ float Hs[32 * 132];   // [m][col] h tile
    const int t = threadIdx.x;
    const int tn = t & 31, tm = t >> 5;
    const int row0 = blockIdx.x * 32;

    // ---- pass 1: h = relu(x @ Wft^T + bft) -> Hs ----
    float acc[4][4] = {};
    for (int kc = 0; kc < 128; kc += 32) {
#pragma unroll
        for (int i = 0; i < 4; i++) {
            int lin = t + i * 256;
            int m = lin >> 5, cc = lin & 31;
            int row = row0 + m;
            As[cc * 36 + m] = (row < M) ? x[(size_t)row * 128 + kc + cc] : 0.f;
        }
#pragma unroll
        for (int i = 0; i < 16; i++) {
            int lin = t + i * 256;
            int cc = lin & 31, j = lin >> 5;
            Ws[cc * 132 + j] = Wft[j * 128 + kc + cc];
        }
        __syncthreads();
#pragma unroll
        for (int cc = 0; cc < 32; cc++) {
            float4 a4 = *(const float4*)(As + cc * 36 + tm * 4);
            float4 b4 = *(const float4*)(Ws + cc * 132 + tn * 4);
            float ar[4] = {a4.x, a4.y, a4.z, a4.w};
            float br[4] = {b4.x, b4.y, b4.z, b4.w};
#pragma unroll
            for (int r = 0; r < 4; r++)
#pragma unroll
                for (int u = 0; u < 4; u++) acc[r][u] += ar[r] * br[u];
        }
        __syncthreads();
    }
    {
        float4 bv = *(const float4*)(bft + tn * 4);
        float bb[4] = {bv.x, bv.y, bv.z, bv.w};
#pragma unroll
        for (int r = 0; r < 4; r++)
#pragma unroll
            for (int u = 0; u < 4; u++)
                Hs[(tm * 4 + r) * 132 + tn * 4 + u] = fmaxf(acc[r][u] + bb[u], 0.f);
    }
    __syncthreads();

    // ---- pass 2: hw = Hs @ Wconv^T + bconv ----
    float acc2[4][4] = {};
    for (int kc = 0; kc < 128; kc += 32) {
#pragma unroll
        for (int i = 0; i < 16; i++) {
            int lin = t + i * 256;
            int cc = lin & 31, j = lin >> 5;
            Ws[cc * 132 + j] = Wconv[j * 128 + kc + cc];
        }
        __syncthreads();
#pragma unroll
        for (int cc = 0; cc < 32; cc++) {
            float4 b4 = *(const float4*)(Ws + cc * 132 + tn * 4);
            float br[4] = {b4.x, b4.y, b4.z, b4.w};
#pragma unroll
            for (int r = 0; r < 4; r++) {
                float a = Hs[(tm * 4 + r) * 132 + kc + cc];   // warp-uniform broadcast
#pragma unroll
                for (int u = 0; u < 4; u++) acc2[r][u] += a * br[u];
            }
        }
        __syncthreads();
    }
    float4 bv = *(const float4*)(bconv + tn * 4);
    float bb[4] = {bv.x, bv.y, bv.z, bv.w};
#pragma unroll
    for (int r = 0; r < 4; r++) {
        int row = row0 + tm * 4 + r;
        if (row < M) {
            float4 o;
            o.x = acc2[r][0] + bb[0]; o.y = acc2[r][1] + bb[1];
            o.z = acc2[r][2] + bb[2]; o.w = acc2[r][3] + bb[3];
            *(float4*)(out + (size_t)row * 128 + tn * 4) = o;
        }
    }
}

// ---------------- edge pass 1: dist, dsum, global max(dist) ----------------
__global__ void edge_prep1(const int* __restrict__ ei, const float* __restrict__ pos) {
    int e = blockIdx.x * blockDim.x + threadIdx.x;
    float d = 0.f;
    if (e < EE) {
        int s = ei[e], t = ei[EE + e];
        float dx = pos[s * 3 + 0] - pos[t * 3 + 0];
        float dy = pos[s * 3 + 1] - pos[t * 3 + 1];
        float dz = pos[s * 3 + 2] - pos[t * 3 + 2];
        d = sqrtf(dx * dx + dy * dy + dz * dz);
        g_dist[e] = d;
        g_dsum[e] = (dx + dy + dz) / (d + 1e-8f);
    }
#pragma unroll
    for (int o = 16; o; o >>= 1) d = fmaxf(d, __shfl_xor_sync(0xffffffffu, d, o));
    __shared__ float wm[8];
    if ((threadIdx.x & 31) == 0) wm[threadIdx.x >> 5] = d;
    __syncthreads();
    if (threadIdx.x < 8) {
        d = wm[threadIdx.x];
#pragma unroll
        for (int o = 4; o; o >>= 1) d = fmaxf(d, __shfl_xor_sync(0xffu, d, o));
        if (threadIdx.x == 0) atomicMax(&g_maxd, __float_as_uint(d));
    }
}

// ---------------- CSR build: histogram, 3-kernel scan, slot fill ----------------
__global__ void hist_kernel(const int* __restrict__ ei) {
    int e = blockIdx.x * blockDim.x + threadIdx.x;
    if (e < EE) atomicAdd(&g_deg[ei[EE + e]], 1);
}

__global__ __launch_bounds__(SCAN_B) void scan1_kernel() {
    __shared__ int sh[SCAN_B];
    int i = blockIdx.x * SCAN_B + threadIdx.x;
    sh[threadIdx.x] = (i < NN) ? g_deg[i] : 0;
    __syncthreads();
#pragma unroll
    for (int off = 1; off < SCAN_B; off <<= 1) {
        int add = (threadIdx.x >= off) ? sh[threadIdx.x - off] : 0;
        __syncthreads();
        sh[threadIdx.x] += add;
        __syncthreads();
    }
    if (i < NN) g_scan[i] = sh[threadIdx.x];
    if (threadIdx.x == SCAN_B - 1) g_btot[blockIdx.x] = sh[SCAN_B - 1];
}

__global__ void scan2_kernel() {
    __shared__ int sh[64];
    int t = threadIdx.x;
    sh[t] = (t < NCHUNK) ? g_btot[t] : 0;
    __syncthreads();
#pragma unroll
    for (int off = 1; off < 64; off <<= 1) {
        int add = (t >= off) ? sh[t - off] : 0;
        __syncthreads();
        sh[t] += add;
        __syncthreads();
    }
    if (t < NCHUNK) g_btot[t] = sh[t];   // inclusive block totals
}

__global__ __launch_bounds__(SCAN_B) void scan3_kernel() {
    int i = blockIdx.x * SCAN_B + threadIdx.x;
    if (i < NN) {
        int boff = (blockIdx.x > 0) ? g_btot[blockIdx.x - 1] : 0;
        g_base[i + 1] = g_scan[i] + boff;
    }
    if (i == 0) g_base[0] = 0;
}

__global__ void fill_kernel(const int* __restrict__ ei,
                            const float* __restrict__ vf_p, const float* __restrict__ vmax_p) {
    int e = blockIdx.x * blockDim.x + threadIdx.x;
    if (e >= EE) return;
    int s = ei[e], t = ei[EE + e];
    float md = __uint_as_float(g_maxd);
    float r = g_dist[e] / md;
    float ds = g_dsum[e];
    float vf = vf_p[0];
    float ab[KK];
#pragma unroll
    for (int k = 0; k < KK; k++) {
        float v = vf * fminf(r, vmax_p[k]);
        ab[k] = sqrtf(1.f - v * v + 1e-8f) / (1.f + v * ds);
    }
    int slot = g_base[t] + atomicAdd(&g_cur[t], 1);
    g_srcs[slot] = s;
    g_ab4[slot] = make_float4(ab[0], ab[1], ab[2], ab[3]);
}

// ---------------- gather-aggregate: one warp per node, 4 views in registers ----------------
__global__ __launch_bounds__(256) void gather_kernel() {
    int gt = blockIdx.x * blockDim.x + threadIdx.x;
    int warp = gt >> 5, lane = gt & 31;
    int nwarps = (gridDim.x * blockDim.x) >> 5;
    const float4* hw4 = (const float4*)g_hw;
    for (int node = warp; node < NN; node += nwarps) {
        int beg = g_base[node], end = g_base[node + 1];
        float4 acc0 = {0.f, 0.f, 0.f, 0.f}, acc1 = acc0, acc2 = acc0, acc3 = acc0;
        int e = beg;
        for (; e + 1 < end; e += 2) {
            int s0 = g_srcs[e], s1 = g_srcs[e + 1];
            float4 ab0 = g_ab4[e], ab1 = g_ab4[e + 1];
            float4 a0 = hw4[(size_t)s0 * 32 + lane];
            float4 a1 = hw4[(size_t)s1 * 32 + lane];
            acc0.x += a0.x * ab0.x; acc0.y += a0.y * ab0.x; acc0.z += a0.z * ab0.x; acc0.w += a0.w * ab0.x;
            acc1.x += a0.x * ab0.y; acc1.y += a0.y * ab0.y; acc1.z += a0.z * ab0.y; acc1.w += a0.w * ab0.y;
            acc2.x += a0.x * ab0.z; acc2.y += a0.y * ab0.z; acc2.z += a0.z * ab0.z; acc2.w += a0.w * ab0.z;
            acc3.x += a0.x * ab0.w; acc3.y += a0.y * ab0.w; acc3.z += a0.z * ab0.w; acc3.w += a0.w * ab0.w;
            acc0.x += a1.x * ab1.x; acc0.y += a1.y * ab1.x; acc0.z += a1.z * ab1.x; acc0.w += a1.w * ab1.x;
            acc1.x += a1.x * ab1.y; acc1.y += a1.y * ab1.y; acc1.z += a1.z * ab1.y; acc1.w += a1.w * ab1.y;
            acc2.x += a1.x * ab1.z; acc2.y += a1.y * ab1.z; acc2.z += a1.z * ab1.z; acc2.w += a1.w * ab1.z;
            acc3.x += a1.x * ab1.w; acc3.y += a1.y * ab1.w; acc3.z += a1.z * ab1.w; acc3.w += a1.w * ab1.w;
        }
        if (e < end) {
            int s0 = g_srcs[e];
            float4 ab0 = g_ab4[e];
            float4 a0 = hw4[(size_t)s0 * 32 + lane];
            acc0.x += a0.x * ab0.x; acc0.y += a0.y * ab0.x; acc0.z += a0.z * ab0.x; acc0.w += a0.w * ab0.x;
            acc1.x += a0.x * ab0.y; acc1.y += a0.y * ab0.y; acc1.z += a0.z * ab0.y; acc1.w += a0.w * ab0.y;
            acc2.x += a0.x * ab0.z; acc2.y += a0.y * ab0.z; acc2.z += a0.z * ab0.z; acc2.w += a0.w * ab0.z;
            acc3.x += a0.x * ab0.w; acc3.y += a0.y * ab0.w; acc3.z += a0.z * ab0.w; acc3.w += a0.w * ab0.w;
        }
        ((float4*)g_agg)[((size_t)0 * NN + node) * 32 + lane] = acc0;
        ((float4*)g_agg)[((size_t)1 * NN + node) * 32 + lane] = acc1;
        ((float4*)g_agg)[((size_t)2 * NN + node) * 32 + lane] = acc2;
        ((float4*)g_agg)[((size_t)3 * NN + node) * 32 + lane] = acc3;
    }
}

// ---------------- BN statistics ----------------
__global__ void bn_stats_kernel() {
    int f = threadIdx.x;                       // 0..127
    int k = blockIdx.y;                        // 0..3
    int per = (NN + gridDim.x - 1) / gridDim.x;
    int n0 = blockIdx.x * per;
    int n1 = min(n0 + per, NN);
    float s = 0.f, q = 0.f;
    const float* base = g_agg + (size_t)k * NN * 128 + f;
    for (int n = n0; n < n1; n++) {
        float v = base[(size_t)n * 128];
        s += v; q += v * v;
    }
    atomicAdd(&g_sum[k * 128 + f], s);
    atomicAdd(&g_sumsq[k * 128 + f], q);
}

__global__ void bn_final_kernel(const float* __restrict__ bg, const float* __restrict__ bb,
                                const float* __restrict__ att) {
    int c = threadIdx.x;  // 0..511
    float mean = g_sum[c] * (1.f / NN);
    float var = g_sumsq[c] * (1.f / NN) - mean * mean;
    float rstd = rsqrtf(fmaxf(var, 0.f) + 1e-5f);
    float sc = rstd * bg[c];
    g_sc[c] = sc;
    g_tc[c] = bb[c] - mean * sc;
    g_ac[c] = att[c];
}

// ---------------- fused tail: bn+relu+att -> GEMM1 -> LN+relu -> GEMM2 -> out ----------------
__global__ __launch_bounds__(256) void fused_out_kernel(
    const float* __restrict__ W1, const float* __restrict__ b1,
    const float* __restrict__ lng, const float* __restrict__ lnb,
    const float* __restrict__ W2, const float* __restrict__ b2,
    float* __restrict__ out) {
    __shared__ float smem[10432];
    float* As = smem;                         // [32][36]
    float* Bs = smem + 1152;                  // [32][260]
    float* Cs = smem;                         // [32][260] (reuse)
    float* Ws2 = smem + 8320;                 // [16][132]
    const int t = threadIdx.x;
    const int tn = t & 31, tm = t >> 5;
    const int row0 = blockIdx.x * 32;

    float acc[4][8] = {};
    for (int ch = 0; ch < 16; ch++) {
        int c0 = ch * 32;
#pragma unroll
        for (int i = 0; i < 4; i++) {
            int lin = t + i * 256;
            int m = lin >> 5, cc = lin & 31;
            int cg = c0 + cc;
            int k = cg >> 7, f = cg & 127;
            int row = row0 + m;
            float v = 0.f;
            if (row < NN) {
                float a = g_agg[((size_t)k * NN + row) * 128 + f];
                v = fmaxf(a * g_sc[cg] + g_tc[cg], 0.f) * g_ac[cg];
            }
            As[cc * 36 + m] = v;
        }
#pragma unroll
        for (int i = 0; i < 32; i++) {
            int lin = t + i * 256;
            int cc = lin & 31, j = lin >> 5;
            Bs[cc * 260 + j] = W1[(size_t)j * 512 + c0 + cc];
        }
        __syncthreads();
#pragma unroll
        for (int cc = 0; cc < 32; cc++) {
            float4 a4 = *(const float4*)(As + cc * 36 + tm * 4);
            const float* bp = Bs + cc * 260 + tn * 8;
            float4 bA = *(const float4*)bp;
            float4 bB = *(const float4*)(bp + 4);
            float ar[4] = {a4.x, a4.y, a4.z, a4.w};
            float br[8] = {bA.x, bA.y, bA.z, bA.w, bB.x, bB.y, bB.z, bB.w};
#pragma unroll
            for (int r = 0; r < 4; r++)
#pragma unroll
                for (int u = 0; u < 8; u++) acc[r][u] += ar[r] * br[u];
        }
        __syncthreads();
    }

    float bb_[8], lg[8], lb[8];
#pragma unroll
    for (int u = 0; u < 8; u++) {
        int col = tn * 8 + u;
        bb_[u] = b1[col]; lg[u] = lng[col]; lb[u] = lnb[col];
    }
#pragma unroll
    for (int r = 0; r < 4; r++) {
        float s = 0.f, q = 0.f;
#pragma unroll
        for (int u = 0; u < 8; u++) {
            acc[r][u] += bb_[u];
            s += acc[r][u];
            q += acc[r][u] * acc[r][u];
        }
#pragma unroll
        for (int o = 16; o; o >>= 1) {
            s += __shfl_xor_sync(0xffffffffu, s, o);
            q += __shfl_xor_sync(0xffffffffu, q, o);
        }
        float mu = s * (1.f / 256.f);
        float var = q * (1.f / 256.f) - mu * mu;
        float rstd = rsqrtf(fmaxf(var, 0.f) + 1e-5f);
#pragma unroll
        for (int u = 0; u < 8; u++)
            acc[r][u] = fmaxf((acc[r][u] - mu) * rstd * lg[u] + lb[u], 0.f);
    }
#pragma unroll
    for (int r = 0; r < 4; r++) {
        float* cp = Cs + (tm * 4 + r) * 260 + tn * 8;
        *(float4*)cp       = make_float4(acc[r][0], acc[r][1], acc[r][2], acc[r][3]);
        *(float4*)(cp + 4) = make_float4(acc[r][4], acc[r][5], acc[r][6], acc[r][7]);
    }
    __syncthreads();

    float acc2[4][4] = {};
    for (int ch = 0; ch < 16; ch++) {
        int c0 = ch * 16;
#pragma unroll
        for (int i = 0; i < 8; i++) {
            int lin = t + i * 256;
            int cc = lin & 15, j = lin >> 4;
            Ws2[cc * 132 + j] = W2[j * 256 + c0 + cc];
        }
        __syncthreads();
#pragma unroll
        for (int cc = 0; cc < 16; cc++) {
            float4 b4 = *(const float4*)(Ws2 + cc * 132 + tn * 4);
            float br[4] = {b4.x, b4.y, b4.z, b4.w};
#pragma unroll
            for (int r = 0; r < 4; r++) {
                float a = Cs[(tm * 4 + r) * 260 + c0 + cc];
#pragma unroll
                for (int u = 0; u < 4; u++) acc2[r][u] += a * br[u];
            }
        }
        __syncthreads();
    }
    float4 b2v = *(const float4*)(b2 + tn * 4);
    float b2r[4] = {b2v.x, b2v.y, b2v.z, b2v.w};
#pragma unroll
    for (int r = 0; r < 4; r++) {
        int row = row0 + tm * 4 + r;
        if (row < NN) {
            float4 o;
            o.x = acc2[r][0] + b2r[0]; o.y = acc2[r][1] + b2r[1];
            o.z = acc2[r][2] + b2r[2]; o.w = acc2[r][3] + b2r[3];
            *(float4*)(out + (size_t)row * 128 + tn * 4) = o;
        }
    }
}

// ---------------- launch ----------------
extern "C" void kernel_launch(void* const* d_in, const int* in_sizes, int n_in,
                              void* d_out, int out_size) {
    const float* x        = (const float*)d_in[0];
    const int*   ei       = (const int*)  d_in[1];
    const float* pos      = (const float*)d_in[2];
    const float* W_ft     = (const float*)d_in[3];
    const float* b_ft     = (const float*)d_in[4];
    const float* W_conv   = (const float*)d_in[5];
    const float* b_conv   = (const float*)d_in[6];
    const float* vf       = (const float*)d_in[7];
    const float* vparams  = (const float*)d_in[8];
    const float* bn_gamma = (const float*)d_in[9];
    const float* bn_beta  = (const float*)d_in[10];
    const float* attention= (const float*)d_in[11];
    const float* W1       = (const float*)d_in[12];
    const float* b1       = (const float*)d_in[13];
    const float* lng      = (const float*)d_in[14];
    const float* lnb      = (const float*)d_in[15];
    const float* W2       = (const float*)d_in[16];
    const float* b2       = (const float*)d_in[17];
    float* out = (float*)d_out;

    void *p_sum, *p_sumsq, *p_maxd, *p_hw, *p_deg, *p_cur;
    cudaGetSymbolAddress(&p_sum, g_sum);
    cudaGetSymbolAddress(&p_sumsq, g_sumsq);
    cudaGetSymbolAddress(&p_maxd, g_maxd);
    cudaGetSymbolAddress(&p_hw, g_hw);
    cudaGetSymbolAddress(&p_deg, g_deg);
    cudaGetSymbolAddress(&p_cur, g_cur);

    cudaMemsetAsync(p_sum, 0, KK * HH * sizeof(float));
    cudaMemsetAsync(p_sumsq, 0, KK * HH * sizeof(float));
    cudaMemsetAsync(p_maxd, 0, sizeof(unsigned));
    cudaMemsetAsync(p_deg, 0, NN * sizeof(int));
    cudaMemsetAsync(p_cur, 0, NN * sizeof(int));

    // stage 1 (fused): hw = relu(x @ W_ft^T + b_ft) @ W_conv^T + b_conv
    mlp2_kernel<<<(NN + 31) / 32, 256>>>(x, W_ft, b_ft, W_conv, b_conv, (float*)p_hw, NN);

    // edge geometry + CSR build
    edge_prep1<<<(EE + 255) / 256, 256>>>(ei, pos);
    hist_kernel<<<(EE + 255) / 256, 256>>>(ei);
    scan1_kernel<<<NCHUNK, SCAN_B>>>();
    scan2_kernel<<<1, 64>>>();
    scan3_kernel<<<NCHUNK, SCAN_B>>>();
    fill_kernel<<<(EE + 255) / 256, 256>>>(ei, vf, vparams);

    // gather-aggregate all 4 views (replaces atomic scatter)
    gather_kernel<<<1024, 256>>>();

    // batch-norm statistics and fold
    bn_stats_kernel<<<dim3(128, KK), 128>>>();
    bn_final_kernel<<<1, KK * HH>>>(bn_gamma, bn_beta, attention);

    // fused tail
    fused_out_kernel<<<(NN + 31) / 32, 256>>>(W1, b1, lng, lnb, W2, b2, out);
}